// round 4
// baseline (speedup 1.0000x reference)
#include <cuda_runtime.h>
#include <cuda_bf16.h>
#include <cstdint>

#define N_NODES 50000
#define N_EDGES 800000
#define IN_F    128
#define OUT_F   256
#define PITCH   136   // bf16 per padded row; 68 words mod 32 = 4 -> conflict-free frags

// ---------------------------------------------------------------------------
// Device scratch (no allocs allowed)
// ---------------------------------------------------------------------------
__device__ __align__(16) __nv_bfloat16 g_Bhi[OUT_F * PITCH];   // W^T hi image
__device__ __align__(16) __nv_bfloat16 g_Blo[OUT_F * PITCH];   // W^T lo image
__device__ int   g_cnt[N_NODES];
__device__ int   g_off[N_NODES + 1];
__device__ int   g_cur[N_NODES];
__device__ __align__(8) uint2 g_edge[N_EDGES];                 // {col, val bits}

// ---------------------------------------------------------------------------
// K1: zero counts + convert W -> padded bf16 hi/lo images of W^T.
// ---------------------------------------------------------------------------
__global__ void prep_kernel(const float* __restrict__ W) {
    const int tid = blockIdx.x * blockDim.x + threadIdx.x;
    for (int i = tid; i < N_NODES; i += gridDim.x * blockDim.x) g_cnt[i] = 0;

    if (blockIdx.x < 32) {   // 32*256*4 = 32768 = IN_F*OUT_F
        const int base = (blockIdx.x * 256 + threadIdx.x) * 4;   // idx = k*256+n
        const float4 w = *reinterpret_cast<const float4*>(W + base);
        const float f[4] = {w.x, w.y, w.z, w.w};
        #pragma unroll
        for (int j = 0; j < 4; j++) {
            const int idx = base + j;
            const int k = idx >> 8;
            const int n = idx & 255;
            const __nv_bfloat16 h = __float2bfloat16(f[j]);
            const __nv_bfloat16 l = __float2bfloat16(f[j] - __bfloat162float(h));
            g_Bhi[n * PITCH + k] = h;
            g_Blo[n * PITCH + k] = l;
        }
    }
}

// ---------------------------------------------------------------------------
// K2: histogram of edge destination rows.
// ---------------------------------------------------------------------------
__global__ void hist_kernel(const int* __restrict__ erow) {
    const int tid = blockIdx.x * blockDim.x + threadIdx.x;
    for (int e = tid; e < N_EDGES; e += gridDim.x * blockDim.x)
        atomicAdd(&g_cnt[erow[e]], 1);
}

// ---------------------------------------------------------------------------
// K3: single-block exclusive scan over g_cnt -> g_off, g_cur.
// ---------------------------------------------------------------------------
#define SCAN_T 1024
#define CHUNK  49            // 1024*49 = 50176 >= 50000
__global__ __launch_bounds__(SCAN_T, 1)
void scan_kernel() {
    __shared__ int ssum[SCAN_T];
    const int tid = threadIdx.x;
    const int base = tid * CHUNK;

    int sum = 0;
    #pragma unroll 7
    for (int i = 0; i < CHUNK; i++) {
        const int idx = base + i;
        if (idx < N_NODES) sum += g_cnt[idx];
    }
    ssum[tid] = sum;
    __syncthreads();
    #pragma unroll
    for (int d = 1; d < SCAN_T; d <<= 1) {
        int v = (tid >= d) ? ssum[tid - d] : 0;
        __syncthreads();
        ssum[tid] += v;
        __syncthreads();
    }
    int running = ssum[tid] - sum;   // exclusive offset for this chunk
    #pragma unroll 7
    for (int i = 0; i < CHUNK; i++) {
        const int idx = base + i;
        if (idx < N_NODES) {
            g_off[idx] = running;
            g_cur[idx] = running;
            running += g_cnt[idx];
        }
    }
    if (tid == SCAN_T - 1) g_off[N_NODES] = N_EDGES;
}

// ---------------------------------------------------------------------------
// K4: bin edges into CSR order (packed col+val).
// ---------------------------------------------------------------------------
__global__ void bin_kernel(const int*   __restrict__ erow,
                           const int*   __restrict__ ecol,
                           const float* __restrict__ eval) {
    const int tid = blockIdx.x * blockDim.x + threadIdx.x;
    for (int e = tid; e < N_EDGES; e += gridDim.x * blockDim.x) {
        const int r = erow[e];
        const int pos = atomicAdd(&g_cur[r], 1);
        g_edge[pos] = make_uint2((uint32_t)ecol[e], __float_as_uint(eval[e]));
    }
}

// ---------------------------------------------------------------------------
// K5: fused gather-aggregate + mma.sync bf16 split GEMM + bias.
//   agg[128,128] built in smem (hi/lo bf16), then
//   out = Ahi@Bhi + Ahi@Blo + Alo@Bhi + b   (fp32 accum)
// 256 threads = 8 warps (2x4 grid), warp tile 64x64, mma.m16n8k16.
// ---------------------------------------------------------------------------
#define GT 256
#define SM_BIAS 0
#define SM_AHI  1024
#define SM_ALO  (SM_AHI + 128 * PITCH * 2)
#define SM_BHI  (SM_ALO + 128 * PITCH * 2)
#define SM_BLO  (SM_BHI + OUT_F * PITCH * 2)
#define SM_TOT  (SM_BLO + OUT_F * PITCH * 2)   // 209920 B

__device__ __forceinline__ void mma16816(float c[4], uint32_t a0, uint32_t a1,
                                         uint32_t a2, uint32_t a3,
                                         uint32_t b0, uint32_t b1) {
    asm volatile(
        "mma.sync.aligned.m16n8k16.row.col.f32.bf16.bf16.f32 "
        "{%0,%1,%2,%3}, {%4,%5,%6,%7}, {%8,%9}, {%0,%1,%2,%3};"
        : "+f"(c[0]), "+f"(c[1]), "+f"(c[2]), "+f"(c[3])
        : "r"(a0), "r"(a1), "r"(a2), "r"(a3), "r"(b0), "r"(b1));
}

__device__ __forceinline__ uint32_t pack_hi(float a, float b) {
    __nv_bfloat162 p = __halves2bfloat162(__float2bfloat16(a), __float2bfloat16(b));
    return *reinterpret_cast<uint32_t*>(&p);
}
__device__ __forceinline__ uint32_t pack_lo(float a, float b) {
    const __nv_bfloat16 ha = __float2bfloat16(a);
    const __nv_bfloat16 hb = __float2bfloat16(b);
    __nv_bfloat162 p = __halves2bfloat162(
        __float2bfloat16(a - __bfloat162float(ha)),
        __float2bfloat16(b - __bfloat162float(hb)));
    return *reinterpret_cast<uint32_t*>(&p);
}

__global__ __launch_bounds__(GT, 1)
void fused_gemm_kernel(const float* __restrict__ x,
                       const float* __restrict__ bias,
                       float*       __restrict__ out) {
    extern __shared__ char smem[];
    const int t    = threadIdx.x;
    const int lane = t & 31;
    const int wid  = t >> 5;
    const int rowbase = blockIdx.x * 128;

    float* bias_s = reinterpret_cast<float*>(smem + SM_BIAS);
    __nv_bfloat16* Ahi = reinterpret_cast<__nv_bfloat16*>(smem + SM_AHI);
    __nv_bfloat16* Alo = reinterpret_cast<__nv_bfloat16*>(smem + SM_ALO);
    __nv_bfloat16* Bhi = reinterpret_cast<__nv_bfloat16*>(smem + SM_BHI);
    __nv_bfloat16* Blo = reinterpret_cast<__nv_bfloat16*>(smem + SM_BLO);

    if (t < 64)
        reinterpret_cast<float4*>(bias_s)[t] =
            reinterpret_cast<const float4*>(bias)[t];

    // Copy W^T hi/lo images (L2-resident): 2 x 4352 uint4.
    {
        const uint4* sh = reinterpret_cast<const uint4*>(g_Bhi);
        const uint4* sl = reinterpret_cast<const uint4*>(g_Blo);
        uint4* dh = reinterpret_cast<uint4*>(Bhi);
        uint4* dl = reinterpret_cast<uint4*>(Blo);
        #pragma unroll
        for (int i = 0; i < 17; i++) {
            dh[t + i * GT] = sh[t + i * GT];
            dl[t + i * GT] = sl[t + i * GT];
        }
    }

    // ---- gather-aggregate phase: one warp per row, 16 rows per warp ----
    for (int rr = wid; rr < 128; rr += 8) {
        const int row = rowbase + rr;
        float4 acc = make_float4(0.f, 0.f, 0.f, 0.f);

        if (row < N_NODES) {
            const int beg = g_off[row];
            const int end = g_off[row + 1];

            for (int base = beg; base < end; base += 32) {
                const int ee = base + lane;
                uint2 ed = make_uint2(0u, 0u);
                if (ee < end) ed = g_edge[ee];
                const int cnt = min(32, end - base);

                int j = 0;
                for (; j + 4 <= cnt; j += 4) {
                    const uint32_t c0 = __shfl_sync(~0u, ed.x, j + 0);
                    const uint32_t c1 = __shfl_sync(~0u, ed.x, j + 1);
                    const uint32_t c2 = __shfl_sync(~0u, ed.x, j + 2);
                    const uint32_t c3 = __shfl_sync(~0u, ed.x, j + 3);
                    const float v0 = __uint_as_float(__shfl_sync(~0u, ed.y, j + 0));
                    const float v1 = __uint_as_float(__shfl_sync(~0u, ed.y, j + 1));
                    const float v2 = __uint_as_float(__shfl_sync(~0u, ed.y, j + 2));
                    const float v3 = __uint_as_float(__shfl_sync(~0u, ed.y, j + 3));
                    const float4 x0 = __ldg(reinterpret_cast<const float4*>(
                        x + (size_t)c0 * IN_F) + lane);
                    const float4 x1 = __ldg(reinterpret_cast<const float4*>(
                        x + (size_t)c1 * IN_F) + lane);
                    const float4 x2 = __ldg(reinterpret_cast<const float4*>(
                        x + (size_t)c2 * IN_F) + lane);
                    const float4 x3 = __ldg(reinterpret_cast<const float4*>(
                        x + (size_t)c3 * IN_F) + lane);
                    acc.x += v0 * x0.x; acc.y += v0 * x0.y;
                    acc.z += v0 * x0.z; acc.w += v0 * x0.w;
                    acc.x += v1 * x1.x; acc.y += v1 * x1.y;
                    acc.z += v1 * x1.z; acc.w += v1 * x1.w;
                    acc.x += v2 * x2.x; acc.y += v2 * x2.y;
                    acc.z += v2 * x2.z; acc.w += v2 * x2.w;
                    acc.x += v3 * x3.x; acc.y += v3 * x3.y;
                    acc.z += v3 * x3.z; acc.w += v3 * x3.w;
                }
                for (; j < cnt; j++) {
                    const uint32_t c = __shfl_sync(~0u, ed.x, j);
                    const float    v = __uint_as_float(__shfl_sync(~0u, ed.y, j));
                    const float4 xv = __ldg(reinterpret_cast<const float4*>(
                        x + (size_t)c * IN_F) + lane);
                    acc.x += v * xv.x; acc.y += v * xv.y;
                    acc.z += v * xv.z; acc.w += v * xv.w;
                }
            }
        }

        // store hi/lo bf16 fragments: row rr, k = 4*lane .. 4*lane+3
        uint2 wh, wl;
        wh.x = pack_hi(acc.x, acc.y); wh.y = pack_hi(acc.z, acc.w);
        wl.x = pack_lo(acc.x, acc.y); wl.y = pack_lo(acc.z, acc.w);
        *reinterpret_cast<uint2*>(Ahi + rr * PITCH + lane * 4) = wh;
        *reinterpret_cast<uint2*>(Alo + rr * PITCH + lane * 4) = wl;
    }
    __syncthreads();

    // ---- MMA phase: warp grid 2(m) x 4(n); warp tile 64x64 ----
    const int wm = wid >> 2;
    const int wn = wid & 3;
    const int g  = lane >> 2;
    const int tg = lane & 3;
    const int m_base = wm * 64;
    const int n_base = wn * 64;

    float acc[4][8][4];
    #pragma unroll
    for (int mt = 0; mt < 4; mt++)
        #pragma unroll
        for (int nt = 0; nt < 8; nt++)
            #pragma unroll
            for (int j = 0; j < 4; j++)
                acc[mt][nt][j] = 0.f;

    const __nv_bfloat16* Ap[3] = {Ahi, Ahi, Alo};
    const __nv_bfloat16* Bp[3] = {Bhi, Blo, Bhi};

    #pragma unroll
    for (int pass = 0; pass < 3; pass++) {
        const __nv_bfloat16* A = Ap[pass];
        const __nv_bfloat16* B = Bp[pass];
        #pragma unroll
        for (int ks = 0; ks < IN_F; ks += 16) {
            uint32_t af[4][4];
            #pragma unroll
            for (int mt = 0; mt < 4; mt++) {
                const __nv_bfloat16* ar =
                    A + (m_base + mt * 16 + g) * PITCH + ks + tg * 2;
                af[mt][0] = *reinterpret_cast<const uint32_t*>(ar);
                af[mt][1] = *reinterpret_cast<const uint32_t*>(ar + 8 * PITCH);
                af[mt][2] = *reinterpret_cast<const uint32_t*>(ar + 8);
                af[mt][3] = *reinterpret_cast<const uint32_t*>(ar + 8 * PITCH + 8);
            }
            uint32_t bf[8][2];
            #pragma unroll
            for (int nt = 0; nt < 8; nt++) {
                const __nv_bfloat16* br =
                    B + (n_base + nt * 8 + g) * PITCH + ks + tg * 2;
                bf[nt][0] = *reinterpret_cast<const uint32_t*>(br);
                bf[nt][1] = *reinterpret_cast<const uint32_t*>(br + 8);
            }
            #pragma unroll
            for (int mt = 0; mt < 4; mt++)
                #pragma unroll
                for (int nt = 0; nt < 8; nt++)
                    mma16816(acc[mt][nt],
                             af[mt][0], af[mt][1], af[mt][2], af[mt][3],
                             bf[nt][0], bf[nt][1]);
        }
    }

    // ---- epilogue ----
    #pragma unroll
    for (int mt = 0; mt < 4; mt++) {
        const int r0 = rowbase + m_base + mt * 16 + g;
        const int r1 = r0 + 8;
        #pragma unroll
        for (int nt = 0; nt < 8; nt++) {
            const int col = n_base + nt * 8 + tg * 2;
            const float bx = bias_s[col];
            const float by = bias_s[col + 1];
            if (r0 < N_NODES) {
                float2 o = make_float2(acc[mt][nt][0] + bx, acc[mt][nt][1] + by);
                *reinterpret_cast<float2*>(out + (size_t)r0 * OUT_F + col) = o;
            }
            if (r1 < N_NODES) {
                float2 o = make_float2(acc[mt][nt][2] + bx, acc[mt][nt][3] + by);
                *reinterpret_cast<float2*>(out + (size_t)r1 * OUT_F + col) = o;
            }
        }
    }
}

// ---------------------------------------------------------------------------
// Launch
// ---------------------------------------------------------------------------
extern "C" void kernel_launch(void* const* d_in, const int* in_sizes, int n_in,
                              void* d_out, int out_size) {
    const float* x    = (const float*)d_in[0];
    const int*   erow = (const int*)  d_in[1];
    const int*   ecol = (const int*)  d_in[2];
    const float* eval = (const float*)d_in[3];
    const float* W    = (const float*)d_in[4];
    const float* bias = (const float*)d_in[5];
    float* out = (float*)d_out;

    prep_kernel<<<64, 256>>>(W);
    hist_kernel<<<782, 256>>>(erow);
    scan_kernel<<<1, SCAN_T>>>();
    bin_kernel<<<782, 256>>>(erow, ecol, eval);

    cudaFuncSetAttribute(fused_gemm_kernel,
                         cudaFuncAttributeMaxDynamicSharedMemorySize, SM_TOT);
    const int gemm_blocks = (N_NODES + 127) / 128;   // 391
    fused_gemm_kernel<<<gemm_blocks, GT, SM_TOT>>>(x, bias, out);
}

// round 5
// speedup vs baseline: 1.1181x; 1.1181x over previous
#include <cuda_runtime.h>
#include <cuda_bf16.h>
#include <cstdint>

#define N_NODES 50000
#define N_EDGES 800000
#define IN_F    128
#define OUT_F   256
#define PITCH   136   // bf16 per padded row; 68 words mod 32 = 4 -> conflict-free frags

// ---------------------------------------------------------------------------
// Device scratch (no allocs allowed)
// ---------------------------------------------------------------------------
__device__ __align__(16) __nv_bfloat16 g_Bhi[OUT_F * PITCH];
__device__ __align__(16) __nv_bfloat16 g_Blo[OUT_F * PITCH];
__device__ int   g_cnt[N_NODES];
__device__ int   g_off[N_NODES + 1];
__device__ int   g_cur[N_NODES];
__device__ __align__(8) uint2 g_edge[N_EDGES];   // {col, val bits}

// ---------------------------------------------------------------------------
// K1: zero counts + convert W -> padded bf16 hi/lo images of W^T.
// ---------------------------------------------------------------------------
__global__ void prep_kernel(const float* __restrict__ W) {
    const int tid = blockIdx.x * blockDim.x + threadIdx.x;
    for (int i = tid; i < N_NODES; i += gridDim.x * blockDim.x) g_cnt[i] = 0;

    if (blockIdx.x < 32) {   // 32*256*4 = 32768 = IN_F*OUT_F
        const int base = (blockIdx.x * 256 + threadIdx.x) * 4;   // idx = k*256+n
        const float4 w = *reinterpret_cast<const float4*>(W + base);
        const float f[4] = {w.x, w.y, w.z, w.w};
        #pragma unroll
        for (int j = 0; j < 4; j++) {
            const int idx = base + j;
            const int k = idx >> 8;
            const int n = idx & 255;
            const __nv_bfloat16 h = __float2bfloat16(f[j]);
            const __nv_bfloat16 l = __float2bfloat16(f[j] - __bfloat162float(h));
            g_Bhi[n * PITCH + k] = h;
            g_Blo[n * PITCH + k] = l;
        }
    }
}

// ---------------------------------------------------------------------------
// K2: histogram of destination rows (4 edges/thread, int4 load).
// ---------------------------------------------------------------------------
__global__ void hist_kernel(const int* __restrict__ erow) {
    const int base = (blockIdx.x * blockDim.x + threadIdx.x) * 4;
    if (base + 4 <= N_EDGES) {
        const int4 r = __ldg(reinterpret_cast<const int4*>(erow + base));
        atomicAdd(&g_cnt[r.x], 1);
        atomicAdd(&g_cnt[r.y], 1);
        atomicAdd(&g_cnt[r.z], 1);
        atomicAdd(&g_cnt[r.w], 1);
    } else {
        for (int e = base; e < N_EDGES; e++) atomicAdd(&g_cnt[erow[e]], 1);
    }
}

// ---------------------------------------------------------------------------
// K3: single-block exclusive scan over g_cnt -> g_off, g_cur.
// ---------------------------------------------------------------------------
#define SCAN_T 1024
#define CHUNK  49
__global__ __launch_bounds__(SCAN_T, 1)
void scan_kernel() {
    __shared__ int ssum[SCAN_T];
    const int tid = threadIdx.x;
    const int base = tid * CHUNK;

    int sum = 0;
    #pragma unroll 7
    for (int i = 0; i < CHUNK; i++) {
        const int idx = base + i;
        if (idx < N_NODES) sum += g_cnt[idx];
    }
    ssum[tid] = sum;
    __syncthreads();
    #pragma unroll
    for (int d = 1; d < SCAN_T; d <<= 1) {
        int v = (tid >= d) ? ssum[tid - d] : 0;
        __syncthreads();
        ssum[tid] += v;
        __syncthreads();
    }
    int running = ssum[tid] - sum;
    #pragma unroll 7
    for (int i = 0; i < CHUNK; i++) {
        const int idx = base + i;
        if (idx < N_NODES) {
            g_off[idx] = running;
            g_cur[idx] = running;
            running += g_cnt[idx];
        }
    }
    if (tid == SCAN_T - 1) g_off[N_NODES] = N_EDGES;
}

// ---------------------------------------------------------------------------
// K4: bin edges into CSR order (4 edges/thread, vector loads).
// ---------------------------------------------------------------------------
__global__ void bin_kernel(const int*   __restrict__ erow,
                           const int*   __restrict__ ecol,
                           const float* __restrict__ eval) {
    const int base = (blockIdx.x * blockDim.x + threadIdx.x) * 4;
    if (base + 4 <= N_EDGES) {
        const int4   r = __ldg(reinterpret_cast<const int4*>(erow + base));
        const int4   c = __ldg(reinterpret_cast<const int4*>(ecol + base));
        const float4 v = __ldg(reinterpret_cast<const float4*>(eval + base));
        const int p0 = atomicAdd(&g_cur[r.x], 1);
        const int p1 = atomicAdd(&g_cur[r.y], 1);
        const int p2 = atomicAdd(&g_cur[r.z], 1);
        const int p3 = atomicAdd(&g_cur[r.w], 1);
        g_edge[p0] = make_uint2((uint32_t)c.x, __float_as_uint(v.x));
        g_edge[p1] = make_uint2((uint32_t)c.y, __float_as_uint(v.y));
        g_edge[p2] = make_uint2((uint32_t)c.z, __float_as_uint(v.z));
        g_edge[p3] = make_uint2((uint32_t)c.w, __float_as_uint(v.w));
    } else {
        for (int e = base; e < N_EDGES; e++) {
            const int pos = atomicAdd(&g_cur[erow[e]], 1);
            g_edge[pos] = make_uint2((uint32_t)ecol[e], __float_as_uint(eval[e]));
        }
    }
}

// ---------------------------------------------------------------------------
// K5: fused gather-aggregate + mma.sync bf16 split GEMM + bias.
// 512 threads = 16 warps. Gather: 8 rows/warp, 8-way unrolled edge->x chains.
// MMA: warp grid 4(m) x 4(n), warp tile 32x64, mma.m16n8k16, 3 passes.
// ---------------------------------------------------------------------------
#define GT 512
#define SM_BIAS 0
#define SM_AHI  1024
#define SM_ALO  (SM_AHI + 128 * PITCH * 2)
#define SM_BHI  (SM_ALO + 128 * PITCH * 2)
#define SM_BLO  (SM_BHI + OUT_F * PITCH * 2)
#define SM_TOT  (SM_BLO + OUT_F * PITCH * 2)   // 209920 B

__device__ __forceinline__ void mma16816(float c[4], uint32_t a0, uint32_t a1,
                                         uint32_t a2, uint32_t a3,
                                         uint32_t b0, uint32_t b1) {
    asm volatile(
        "mma.sync.aligned.m16n8k16.row.col.f32.bf16.bf16.f32 "
        "{%0,%1,%2,%3}, {%4,%5,%6,%7}, {%8,%9}, {%0,%1,%2,%3};"
        : "+f"(c[0]), "+f"(c[1]), "+f"(c[2]), "+f"(c[3])
        : "r"(a0), "r"(a1), "r"(a2), "r"(a3), "r"(b0), "r"(b1));
}

__device__ __forceinline__ uint32_t pack_hi(float a, float b) {
    __nv_bfloat162 p = __halves2bfloat162(__float2bfloat16(a), __float2bfloat16(b));
    return *reinterpret_cast<uint32_t*>(&p);
}
__device__ __forceinline__ uint32_t pack_lo(float a, float b) {
    const __nv_bfloat16 ha = __float2bfloat16(a);
    const __nv_bfloat16 hb = __float2bfloat16(b);
    __nv_bfloat162 p = __halves2bfloat162(
        __float2bfloat16(a - __bfloat162float(ha)),
        __float2bfloat16(b - __bfloat162float(hb)));
    return *reinterpret_cast<uint32_t*>(&p);
}

__global__ __launch_bounds__(GT, 1)
void fused_gemm_kernel(const float* __restrict__ x,
                       const float* __restrict__ bias,
                       float*       __restrict__ out) {
    extern __shared__ char smem[];
    const int t    = threadIdx.x;
    const int lane = t & 31;
    const int wid  = t >> 5;
    const int rowbase = blockIdx.x * 128;

    float* bias_s = reinterpret_cast<float*>(smem + SM_BIAS);
    __nv_bfloat16* Ahi = reinterpret_cast<__nv_bfloat16*>(smem + SM_AHI);
    __nv_bfloat16* Alo = reinterpret_cast<__nv_bfloat16*>(smem + SM_ALO);
    __nv_bfloat16* Bhi = reinterpret_cast<__nv_bfloat16*>(smem + SM_BHI);
    __nv_bfloat16* Blo = reinterpret_cast<__nv_bfloat16*>(smem + SM_BLO);

    if (t < 64)
        reinterpret_cast<float4*>(bias_s)[t] =
            reinterpret_cast<const float4*>(bias)[t];

    // Copy W^T hi/lo images (L2-resident): 2 x 4352 uint4 over 512 threads.
    {
        const uint4* sh = reinterpret_cast<const uint4*>(g_Bhi);
        const uint4* sl = reinterpret_cast<const uint4*>(g_Blo);
        uint4* dh = reinterpret_cast<uint4*>(Bhi);
        uint4* dl = reinterpret_cast<uint4*>(Blo);
        #pragma unroll
        for (int i = 0; i < 8; i++) {
            dh[t + i * GT] = sh[t + i * GT];
            dl[t + i * GT] = sl[t + i * GT];
        }
        if (t < 4352 - 8 * GT) {
            dh[t + 8 * GT] = sh[t + 8 * GT];
            dl[t + 8 * GT] = sl[t + 8 * GT];
        }
    }

    // ---- gather-aggregate: 8 rows per warp, 8-way unrolled edge chains ----
    #pragma unroll
    for (int i = 0; i < 8; i++) {
        const int rr = wid + i * 16;
        const int row = rowbase + rr;
        float4 acc = make_float4(0.f, 0.f, 0.f, 0.f);

        if (row < N_NODES) {
            const int beg = g_off[row];
            const int end = g_off[row + 1];
            int j = beg;

            for (; j + 8 <= end; j += 8) {
                uint2 e[8];
                #pragma unroll
                for (int u = 0; u < 8; u++) e[u] = __ldg(g_edge + j + u);
                float4 xv[8];
                #pragma unroll
                for (int u = 0; u < 8; u++)
                    xv[u] = __ldg(reinterpret_cast<const float4*>(
                        x + (size_t)e[u].x * IN_F) + lane);
                #pragma unroll
                for (int u = 0; u < 8; u++) {
                    const float v = __uint_as_float(e[u].y);
                    acc.x += v * xv[u].x; acc.y += v * xv[u].y;
                    acc.z += v * xv[u].z; acc.w += v * xv[u].w;
                }
            }
            for (; j < end; j++) {
                const uint2 e = __ldg(g_edge + j);
                const float v = __uint_as_float(e.y);
                const float4 xv = __ldg(reinterpret_cast<const float4*>(
                    x + (size_t)e.x * IN_F) + lane);
                acc.x += v * xv.x; acc.y += v * xv.y;
                acc.z += v * xv.z; acc.w += v * xv.w;
            }
        }

        uint2 wh, wl;
        wh.x = pack_hi(acc.x, acc.y); wh.y = pack_hi(acc.z, acc.w);
        wl.x = pack_lo(acc.x, acc.y); wl.y = pack_lo(acc.z, acc.w);
        *reinterpret_cast<uint2*>(Ahi + rr * PITCH + lane * 4) = wh;
        *reinterpret_cast<uint2*>(Alo + rr * PITCH + lane * 4) = wl;
    }
    __syncthreads();

    // ---- MMA phase: warp grid 4(m) x 4(n); warp tile 32x64 ----
    const int wm = wid >> 2;
    const int wn = wid & 3;
    const int g  = lane >> 2;
    const int tg = lane & 3;
    const int m_base = wm * 32;
    const int n_base = wn * 64;

    float acc[2][8][4];
    #pragma unroll
    for (int mt = 0; mt < 2; mt++)
        #pragma unroll
        for (int nt = 0; nt < 8; nt++)
            #pragma unroll
            for (int j = 0; j < 4; j++)
                acc[mt][nt][j] = 0.f;

    const __nv_bfloat16* Ap[3] = {Ahi, Ahi, Alo};
    const __nv_bfloat16* Bp[3] = {Bhi, Blo, Bhi};

    #pragma unroll
    for (int pass = 0; pass < 3; pass++) {
        const __nv_bfloat16* A = Ap[pass];
        const __nv_bfloat16* B = Bp[pass];
        #pragma unroll
        for (int ks = 0; ks < IN_F; ks += 16) {
            uint32_t af[2][4];
            #pragma unroll
            for (int mt = 0; mt < 2; mt++) {
                const __nv_bfloat16* ar =
                    A + (m_base + mt * 16 + g) * PITCH + ks + tg * 2;
                af[mt][0] = *reinterpret_cast<const uint32_t*>(ar);
                af[mt][1] = *reinterpret_cast<const uint32_t*>(ar + 8 * PITCH);
                af[mt][2] = *reinterpret_cast<const uint32_t*>(ar + 8);
                af[mt][3] = *reinterpret_cast<const uint32_t*>(ar + 8 * PITCH + 8);
            }
            uint32_t bf[8][2];
            #pragma unroll
            for (int nt = 0; nt < 8; nt++) {
                const __nv_bfloat16* br =
                    B + (n_base + nt * 8 + g) * PITCH + ks + tg * 2;
                bf[nt][0] = *reinterpret_cast<const uint32_t*>(br);
                bf[nt][1] = *reinterpret_cast<const uint32_t*>(br + 8);
            }
            #pragma unroll
            for (int mt = 0; mt < 2; mt++)
                #pragma unroll
                for (int nt = 0; nt < 8; nt++)
                    mma16816(acc[mt][nt],
                             af[mt][0], af[mt][1], af[mt][2], af[mt][3],
                             bf[nt][0], bf[nt][1]);
        }
    }

    // ---- epilogue ----
    #pragma unroll
    for (int mt = 0; mt < 2; mt++) {
        const int r0 = rowbase + m_base + mt * 16 + g;
        const int r1 = r0 + 8;
        #pragma unroll
        for (int nt = 0; nt < 8; nt++) {
            const int col = n_base + nt * 8 + tg * 2;
            const float bx = bias_s[col];
            const float by = bias_s[col + 1];
            if (r0 < N_NODES) {
                float2 o = make_float2(acc[mt][nt][0] + bx, acc[mt][nt][1] + by);
                *reinterpret_cast<float2*>(out + (size_t)r0 * OUT_F + col) = o;
            }
            if (r1 < N_NODES) {
                float2 o = make_float2(acc[mt][nt][2] + bx, acc[mt][nt][3] + by);
                *reinterpret_cast<float2*>(out + (size_t)r1 * OUT_F + col) = o;
            }
        }
    }
}

// ---------------------------------------------------------------------------
// Launch
// ---------------------------------------------------------------------------
extern "C" void kernel_launch(void* const* d_in, const int* in_sizes, int n_in,
                              void* d_out, int out_size) {
    const float* x    = (const float*)d_in[0];
    const int*   erow = (const int*)  d_in[1];
    const int*   ecol = (const int*)  d_in[2];
    const float* eval = (const float*)d_in[3];
    const float* W    = (const float*)d_in[4];
    const float* bias = (const float*)d_in[5];
    float* out = (float*)d_out;

    prep_kernel<<<64, 256>>>(W);
    hist_kernel<<<(N_EDGES / 4 + 255) / 256, 256>>>(erow);
    scan_kernel<<<1, SCAN_T>>>();
    bin_kernel<<<(N_EDGES / 4 + 255) / 256, 256>>>(erow, ecol, eval);

    cudaFuncSetAttribute(fused_gemm_kernel,
                         cudaFuncAttributeMaxDynamicSharedMemorySize, SM_TOT);
    const int gemm_blocks = (N_NODES + 127) / 128;   // 391
    fused_gemm_kernel<<<gemm_blocks, GT, SM_TOT>>>(x, bias, out);
}

// round 6
// speedup vs baseline: 2.2254x; 1.9903x over previous
#include <cuda_runtime.h>
#include <cuda_bf16.h>
#include <cstdint>

#define N_NODES 50000
#define N_EDGES 800000
#define IN_F    128
#define OUT_F   256
#define PITCH   136   // bf16 per padded row; 68 words mod 32 = 4 -> conflict-free frags
#define CAP     64    // per-row edge bucket capacity (max degree ~45)
#define OVF_CAP 1024

// ---------------------------------------------------------------------------
// Device scratch (no allocs allowed)
// ---------------------------------------------------------------------------
__device__ float g_agg[(size_t)N_NODES * IN_F];                 // 25.6 MB
__device__ __align__(16) __nv_bfloat16 g_Bhi[OUT_F * PITCH];
__device__ __align__(16) __nv_bfloat16 g_Blo[OUT_F * PITCH];
__device__ int   g_cnt[N_NODES];
__device__ __align__(8)  uint2 g_edge[(size_t)N_NODES * CAP];   // 25.6 MB buckets
__device__ int   g_ovf_cnt;
__device__ __align__(16) uint4 g_ovf[OVF_CAP];                  // {row,col,val,0}

// ---------------------------------------------------------------------------
// K1: zero counts + convert W -> padded bf16 hi/lo images of W^T.
// ---------------------------------------------------------------------------
__global__ void prep_kernel(const float* __restrict__ W) {
    const int tid = blockIdx.x * blockDim.x + threadIdx.x;
    for (int i = tid; i < N_NODES; i += gridDim.x * blockDim.x) g_cnt[i] = 0;
    if (tid == 0) g_ovf_cnt = 0;

    if (blockIdx.x < 32) {   // 32*256*4 = 32768 = IN_F*OUT_F
        const int base = (blockIdx.x * 256 + threadIdx.x) * 4;   // idx = k*256+n
        const float4 w = *reinterpret_cast<const float4*>(W + base);
        const float f[4] = {w.x, w.y, w.z, w.w};
        #pragma unroll
        for (int j = 0; j < 4; j++) {
            const int idx = base + j;
            const int k = idx >> 8;
            const int n = idx & 255;
            const __nv_bfloat16 h = __float2bfloat16(f[j]);
            const __nv_bfloat16 l = __float2bfloat16(f[j] - __bfloat162float(h));
            g_Bhi[n * PITCH + k] = h;
            g_Blo[n * PITCH + k] = l;
        }
    }
}

// ---------------------------------------------------------------------------
// K2: direct binning — atomic slot claim, no histogram/scan needed.
// ---------------------------------------------------------------------------
__global__ void bin_kernel(const int*   __restrict__ erow,
                           const int*   __restrict__ ecol,
                           const float* __restrict__ eval) {
    const int e = blockIdx.x * blockDim.x + threadIdx.x;
    if (e >= N_EDGES) return;
    const int r = __ldg(erow + e);
    const int c = __ldg(ecol + e);
    const float v = __ldg(eval + e);
    const int slot = atomicAdd(&g_cnt[r], 1);
    if (slot < CAP) {
        g_edge[(size_t)r * CAP + slot] =
            make_uint2((uint32_t)c, __float_as_uint(v));
    } else {
        const int p = atomicAdd(&g_ovf_cnt, 1);
        if (p < OVF_CAP)
            g_ovf[p] = make_uint4((uint32_t)r, (uint32_t)c,
                                  __float_as_uint(v), 0u);
    }
}

// ---------------------------------------------------------------------------
// K3: gather-aggregate. One warp per row, high occupancy (no smem).
// Row's edges (<=32 per batch) loaded coalesced once; 4-wide predicated
// shfl->ldg groups keep 4 independent 512B x-loads in flight per warp.
// Writes agg row once (no atomics).
// ---------------------------------------------------------------------------
__global__ __launch_bounds__(256)
void gather_kernel(const float* __restrict__ x) {
    const int lane = threadIdx.x & 31;
    const int wid  = threadIdx.x >> 5;
    const int row  = blockIdx.x * 8 + wid;
    if (row >= N_NODES) return;

    const int cnt = min(__ldg(g_cnt + row), CAP);
    const size_t base = (size_t)row * CAP;

    float4 acc = make_float4(0.f, 0.f, 0.f, 0.f);

    #pragma unroll
    for (int batch = 0; batch < 2; batch++) {
        const int nb = min(cnt - batch * 32, 32);
        if (nb <= 0) break;
        const uint2 ed = __ldg(g_edge + base + batch * 32 + lane);

        for (int j = 0; j < nb; j += 4) {
            uint32_t c[4];
            float    v[4];
            #pragma unroll
            for (int u = 0; u < 4; u++) {
                const bool valid = (j + u) < nb;
                const uint32_t cc = __shfl_sync(~0u, ed.x, (j + u) & 31);
                const uint32_t vv = __shfl_sync(~0u, ed.y, (j + u) & 31);
                c[u] = valid ? cc : 0u;
                v[u] = valid ? __uint_as_float(vv) : 0.f;
            }
            float4 xv[4];
            #pragma unroll
            for (int u = 0; u < 4; u++)
                xv[u] = __ldg(reinterpret_cast<const float4*>(
                    x + (size_t)c[u] * IN_F) + lane);
            #pragma unroll
            for (int u = 0; u < 4; u++) {
                acc.x += v[u] * xv[u].x;
                acc.y += v[u] * xv[u].y;
                acc.z += v[u] * xv[u].z;
                acc.w += v[u] * xv[u].w;
            }
        }
    }

    *reinterpret_cast<float4*>(g_agg + (size_t)row * IN_F + lane * 4) = acc;
}

// ---------------------------------------------------------------------------
// K4: overflow fixup (normally 0 iterations; correctness guarantee).
// ---------------------------------------------------------------------------
__global__ void fixup_kernel(const float* __restrict__ x) {
    const int lane = threadIdx.x & 31;
    const int wid  = threadIdx.x >> 5;
    const int n = min(g_ovf_cnt, OVF_CAP);
    for (int i = wid; i < n; i += 8) {
        const uint4 e = g_ovf[i];
        const float v = __uint_as_float(e.z);
        const float4 xv = __ldg(reinterpret_cast<const float4*>(
            x + (size_t)e.y * IN_F) + lane);
        float* dst = g_agg + (size_t)e.x * IN_F + lane * 4;
        asm volatile("red.global.add.v4.f32 [%0], {%1, %2, %3, %4};"
                     :: "l"(dst),
                        "f"(v * xv.x), "f"(v * xv.y),
                        "f"(v * xv.z), "f"(v * xv.w)
                     : "memory");
    }
}

// ---------------------------------------------------------------------------
// K5: mma.sync bf16 split-precision GEMM + bias (R3 version, proven).
// ---------------------------------------------------------------------------
#define GT 256
#define SM_BIAS 0
#define SM_AHI  1024
#define SM_ALO  (SM_AHI + 128 * PITCH * 2)
#define SM_BHI  (SM_ALO + 128 * PITCH * 2)
#define SM_BLO  (SM_BHI + OUT_F * PITCH * 2)
#define SM_TOT  (SM_BLO + OUT_F * PITCH * 2)   // 209920 B

__device__ __forceinline__ void mma16816(float c[4], uint32_t a0, uint32_t a1,
                                         uint32_t a2, uint32_t a3,
                                         uint32_t b0, uint32_t b1) {
    asm volatile(
        "mma.sync.aligned.m16n8k16.row.col.f32.bf16.bf16.f32 "
        "{%0,%1,%2,%3}, {%4,%5,%6,%7}, {%8,%9}, {%0,%1,%2,%3};"
        : "+f"(c[0]), "+f"(c[1]), "+f"(c[2]), "+f"(c[3])
        : "r"(a0), "r"(a1), "r"(a2), "r"(a3), "r"(b0), "r"(b1));
}

__global__ __launch_bounds__(GT, 1)
void gemm_mma_kernel(const float* __restrict__ bias,
                     float*       __restrict__ out) {
    extern __shared__ char smem[];
    const int t    = threadIdx.x;
    const int lane = t & 31;
    const int wid  = t >> 5;
    const int rowbase = blockIdx.x * 128;

    float* bias_s = reinterpret_cast<float*>(smem + SM_BIAS);
    __nv_bfloat16* Ahi = reinterpret_cast<__nv_bfloat16*>(smem + SM_AHI);
    __nv_bfloat16* Alo = reinterpret_cast<__nv_bfloat16*>(smem + SM_ALO);
    __nv_bfloat16* Bhi = reinterpret_cast<__nv_bfloat16*>(smem + SM_BHI);
    __nv_bfloat16* Blo = reinterpret_cast<__nv_bfloat16*>(smem + SM_BLO);

    if (t < 64)
        reinterpret_cast<float4*>(bias_s)[t] =
            reinterpret_cast<const float4*>(bias)[t];

    {
        const uint4* sh = reinterpret_cast<const uint4*>(g_Bhi);
        const uint4* sl = reinterpret_cast<const uint4*>(g_Blo);
        uint4* dh = reinterpret_cast<uint4*>(Bhi);
        uint4* dl = reinterpret_cast<uint4*>(Blo);
        #pragma unroll
        for (int i = 0; i < 17; i++) {
            dh[t + i * GT] = sh[t + i * GT];
            dl[t + i * GT] = sl[t + i * GT];
        }
    }

    #pragma unroll
    for (int i = 0; i < 8; i++) {
        const int idx = t + i * GT;
        const int kb = idx & 15;
        const int m  = idx >> 4;
        const int row = rowbase + m;

        float f[8];
        if (row < N_NODES) {
            const float4* src = reinterpret_cast<const float4*>(
                g_agg + (size_t)row * IN_F + kb * 8);
            const float4 u = src[0];
            const float4 v = src[1];
            f[0]=u.x; f[1]=u.y; f[2]=u.z; f[3]=u.w;
            f[4]=v.x; f[5]=v.y; f[6]=v.z; f[7]=v.w;
        } else {
            #pragma unroll
            for (int j = 0; j < 8; j++) f[j] = 0.f;
        }

        uint4 wh, wl;
        uint32_t* ph = reinterpret_cast<uint32_t*>(&wh);
        uint32_t* pl = reinterpret_cast<uint32_t*>(&wl);
        #pragma unroll
        for (int j = 0; j < 4; j++) {
            const __nv_bfloat16 h0 = __float2bfloat16(f[2*j]);
            const __nv_bfloat16 h1 = __float2bfloat16(f[2*j+1]);
            const __nv_bfloat16 l0 = __float2bfloat16(f[2*j]   - __bfloat162float(h0));
            const __nv_bfloat16 l1 = __float2bfloat16(f[2*j+1] - __bfloat162float(h1));
            __nv_bfloat162 hp = __halves2bfloat162(h0, h1);
            __nv_bfloat162 lp = __halves2bfloat162(l0, l1);
            ph[j] = *reinterpret_cast<uint32_t*>(&hp);
            pl[j] = *reinterpret_cast<uint32_t*>(&lp);
        }
        *reinterpret_cast<uint4*>(Ahi + m * PITCH + kb * 8) = wh;
        *reinterpret_cast<uint4*>(Alo + m * PITCH + kb * 8) = wl;
    }
    __syncthreads();

    const int wm = wid >> 2;
    const int wn = wid & 3;
    const int g  = lane >> 2;
    const int tg = lane & 3;
    const int m_base = wm * 64;
    const int n_base = wn * 64;

    float acc[4][8][4];
    #pragma unroll
    for (int mt = 0; mt < 4; mt++)
        #pragma unroll
        for (int nt = 0; nt < 8; nt++)
            #pragma unroll
            for (int j = 0; j < 4; j++)
                acc[mt][nt][j] = 0.f;

    const __nv_bfloat16* Ap[3] = {Ahi, Ahi, Alo};
    const __nv_bfloat16* Bp[3] = {Bhi, Blo, Bhi};

    #pragma unroll
    for (int pass = 0; pass < 3; pass++) {
        const __nv_bfloat16* A = Ap[pass];
        const __nv_bfloat16* B = Bp[pass];
        #pragma unroll
        for (int ks = 0; ks < IN_F; ks += 16) {
            uint32_t af[4][4];
            #pragma unroll
            for (int mt = 0; mt < 4; mt++) {
                const __nv_bfloat16* ar =
                    A + (m_base + mt * 16 + g) * PITCH + ks + tg * 2;
                af[mt][0] = *reinterpret_cast<const uint32_t*>(ar);
                af[mt][1] = *reinterpret_cast<const uint32_t*>(ar + 8 * PITCH);
                af[mt][2] = *reinterpret_cast<const uint32_t*>(ar + 8);
                af[mt][3] = *reinterpret_cast<const uint32_t*>(ar + 8 * PITCH + 8);
            }
            uint32_t bf[8][2];
            #pragma unroll
            for (int nt = 0; nt < 8; nt++) {
                const __nv_bfloat16* br =
                    B + (n_base + nt * 8 + g) * PITCH + ks + tg * 2;
                bf[nt][0] = *reinterpret_cast<const uint32_t*>(br);
                bf[nt][1] = *reinterpret_cast<const uint32_t*>(br + 8);
            }
            #pragma unroll
            for (int mt = 0; mt < 4; mt++)
                #pragma unroll
                for (int nt = 0; nt < 8; nt++)
                    mma16816(acc[mt][nt],
                             af[mt][0], af[mt][1], af[mt][2], af[mt][3],
                             bf[nt][0], bf[nt][1]);
        }
    }

    #pragma unroll
    for (int mt = 0; mt < 4; mt++) {
        const int r0 = rowbase + m_base + mt * 16 + g;
        const int r1 = r0 + 8;
        #pragma unroll
        for (int nt = 0; nt < 8; nt++) {
            const int col = n_base + nt * 8 + tg * 2;
            const float bx = bias_s[col];
            const float by = bias_s[col + 1];
            if (r0 < N_NODES) {
                float2 o = make_float2(acc[mt][nt][0] + bx, acc[mt][nt][1] + by);
                *reinterpret_cast<float2*>(out + (size_t)r0 * OUT_F + col) = o;
            }
            if (r1 < N_NODES) {
                float2 o = make_float2(acc[mt][nt][2] + bx, acc[mt][nt][3] + by);
                *reinterpret_cast<float2*>(out + (size_t)r1 * OUT_F + col) = o;
            }
        }
    }
}

// ---------------------------------------------------------------------------
// Launch
// ---------------------------------------------------------------------------
extern "C" void kernel_launch(void* const* d_in, const int* in_sizes, int n_in,
                              void* d_out, int out_size) {
    const float* x    = (const float*)d_in[0];
    const int*   erow = (const int*)  d_in[1];
    const int*   ecol = (const int*)  d_in[2];
    const float* eval = (const float*)d_in[3];
    const float* W    = (const float*)d_in[4];
    const float* bias = (const float*)d_in[5];
    float* out = (float*)d_out;

    prep_kernel<<<128, 256>>>(W);
    bin_kernel<<<(N_EDGES + 255) / 256, 256>>>(erow, ecol, eval);
    gather_kernel<<<(N_NODES + 7) / 8, 256>>>(x);
    fixup_kernel<<<1, 256>>>(x);

    cudaFuncSetAttribute(gemm_mma_kernel,
                         cudaFuncAttributeMaxDynamicSharedMemorySize, SM_TOT);
    const int gemm_blocks = (N_NODES + 127) / 128;   // 391
    gemm_mma_kernel<<<gemm_blocks, GT, SM_TOT>>>(bias, out);
}

// round 7
// speedup vs baseline: 2.2345x; 1.0041x over previous
#include <cuda_runtime.h>
#include <cuda_bf16.h>
#include <cstdint>

#define N_NODES 50000
#define N_EDGES 800000
#define IN_F    128
#define OUT_F   256
#define PITCH   136   // bf16 per padded row; 68 words mod 32 = 4 -> conflict-free frags
#define CAP     64    // per-row edge bucket capacity (max degree ~45)
#define OVF_CAP 1024

// ---------------------------------------------------------------------------
// Device scratch (no allocs allowed)
// ---------------------------------------------------------------------------
__device__ float g_agg[(size_t)N_NODES * IN_F];                 // 25.6 MB
__device__ __align__(16) __nv_bfloat16 g_Bhi[OUT_F * PITCH];
__device__ __align__(16) __nv_bfloat16 g_Blo[OUT_F * PITCH];
__device__ int   g_cnt[N_NODES];
__device__ __align__(8)  uint2 g_edge[(size_t)N_NODES * CAP];   // 25.6 MB buckets
__device__ int   g_ovf_cnt;
__device__ __align__(16) uint4 g_ovf[OVF_CAP];                  // {row,col,val,0}

// ---------------------------------------------------------------------------
// K1: zero counts + convert W -> padded bf16 hi/lo images of W^T.
// ---------------------------------------------------------------------------
__global__ void prep_kernel(const float* __restrict__ W) {
    const int tid = blockIdx.x * blockDim.x + threadIdx.x;
    for (int i = tid; i < N_NODES; i += gridDim.x * blockDim.x) g_cnt[i] = 0;
    if (tid == 0) g_ovf_cnt = 0;

    if (blockIdx.x < 32) {   // 32*256*4 = 32768 = IN_F*OUT_F
        const int base = (blockIdx.x * 256 + threadIdx.x) * 4;   // idx = k*256+n
        const float4 w = *reinterpret_cast<const float4*>(W + base);
        const float f[4] = {w.x, w.y, w.z, w.w};
        #pragma unroll
        for (int j = 0; j < 4; j++) {
            const int idx = base + j;
            const int k = idx >> 8;
            const int n = idx & 255;
            const __nv_bfloat16 h = __float2bfloat16(f[j]);
            const __nv_bfloat16 l = __float2bfloat16(f[j] - __bfloat162float(h));
            g_Bhi[n * PITCH + k] = h;
            g_Blo[n * PITCH + k] = l;
        }
    }
}

// ---------------------------------------------------------------------------
// K2: direct binning — atomic slot claim, 4 edges/thread for ILP.
// ---------------------------------------------------------------------------
__device__ __forceinline__ void bin_one(int r, int c, float v) {
    const int slot = atomicAdd(&g_cnt[r], 1);
    if (slot < CAP) {
        g_edge[(size_t)r * CAP + slot] =
            make_uint2((uint32_t)c, __float_as_uint(v));
    } else {
        const int p = atomicAdd(&g_ovf_cnt, 1);
        if (p < OVF_CAP)
            g_ovf[p] = make_uint4((uint32_t)r, (uint32_t)c,
                                  __float_as_uint(v), 0u);
    }
}

__global__ void bin_kernel(const int*   __restrict__ erow,
                           const int*   __restrict__ ecol,
                           const float* __restrict__ eval) {
    const int base = (blockIdx.x * blockDim.x + threadIdx.x) * 4;
    if (base + 4 <= N_EDGES) {
        const int4   r = __ldg(reinterpret_cast<const int4*>(erow + base));
        const int4   c = __ldg(reinterpret_cast<const int4*>(ecol + base));
        const float4 v = __ldg(reinterpret_cast<const float4*>(eval + base));
        // 4 independent atomic+store chains
        const int s0 = atomicAdd(&g_cnt[r.x], 1);
        const int s1 = atomicAdd(&g_cnt[r.y], 1);
        const int s2 = atomicAdd(&g_cnt[r.z], 1);
        const int s3 = atomicAdd(&g_cnt[r.w], 1);
        if (s0 < CAP) g_edge[(size_t)r.x * CAP + s0] = make_uint2((uint32_t)c.x, __float_as_uint(v.x));
        if (s1 < CAP) g_edge[(size_t)r.y * CAP + s1] = make_uint2((uint32_t)c.y, __float_as_uint(v.y));
        if (s2 < CAP) g_edge[(size_t)r.z * CAP + s2] = make_uint2((uint32_t)c.z, __float_as_uint(v.z));
        if (s3 < CAP) g_edge[(size_t)r.w * CAP + s3] = make_uint2((uint32_t)c.w, __float_as_uint(v.w));
        // rare overflow path
        if (s0 >= CAP) { const int p = atomicAdd(&g_ovf_cnt, 1); if (p < OVF_CAP) g_ovf[p] = make_uint4((uint32_t)r.x, (uint32_t)c.x, __float_as_uint(v.x), 0u); }
        if (s1 >= CAP) { const int p = atomicAdd(&g_ovf_cnt, 1); if (p < OVF_CAP) g_ovf[p] = make_uint4((uint32_t)r.y, (uint32_t)c.y, __float_as_uint(v.y), 0u); }
        if (s2 >= CAP) { const int p = atomicAdd(&g_ovf_cnt, 1); if (p < OVF_CAP) g_ovf[p] = make_uint4((uint32_t)r.z, (uint32_t)c.z, __float_as_uint(v.z), 0u); }
        if (s3 >= CAP) { const int p = atomicAdd(&g_ovf_cnt, 1); if (p < OVF_CAP) g_ovf[p] = make_uint4((uint32_t)r.w, (uint32_t)c.w, __float_as_uint(v.w), 0u); }
    } else {
        for (int e = base; e < N_EDGES; e++)
            bin_one(__ldg(erow + e), __ldg(ecol + e), __ldg(eval + e));
    }
}

// ---------------------------------------------------------------------------
// K3: gather-aggregate. One warp per row, high occupancy (no smem).
// Overflow edges (rows with cnt > CAP) handled inline by the owning warp,
// so no separate fixup kernel is needed.
// ---------------------------------------------------------------------------
__global__ __launch_bounds__(256)
void gather_kernel(const float* __restrict__ x) {
    const int lane = threadIdx.x & 31;
    const int wid  = threadIdx.x >> 5;
    const int row  = blockIdx.x * 8 + wid;
    if (row >= N_NODES) return;

    const int raw_cnt = __ldg(g_cnt + row);
    const int cnt = min(raw_cnt, CAP);
    const size_t base = (size_t)row * CAP;

    float4 acc = make_float4(0.f, 0.f, 0.f, 0.f);

    #pragma unroll
    for (int batch = 0; batch < 2; batch++) {
        const int nb = min(cnt - batch * 32, 32);
        if (nb <= 0) break;
        const uint2 ed = __ldg(g_edge + base + batch * 32 + lane);

        for (int j = 0; j < nb; j += 4) {
            uint32_t c[4];
            float    v[4];
            #pragma unroll
            for (int u = 0; u < 4; u++) {
                const bool valid = (j + u) < nb;
                const uint32_t cc = __shfl_sync(~0u, ed.x, (j + u) & 31);
                const uint32_t vv = __shfl_sync(~0u, ed.y, (j + u) & 31);
                c[u] = valid ? cc : 0u;
                v[u] = valid ? __uint_as_float(vv) : 0.f;
            }
            float4 xv[4];
            #pragma unroll
            for (int u = 0; u < 4; u++)
                xv[u] = __ldg(reinterpret_cast<const float4*>(
                    x + (size_t)c[u] * IN_F) + lane);
            #pragma unroll
            for (int u = 0; u < 4; u++) {
                acc.x += v[u] * xv[u].x;
                acc.y += v[u] * xv[u].y;
                acc.z += v[u] * xv[u].z;
                acc.w += v[u] * xv[u].w;
            }
        }
    }

    // Inline overflow handling: only rows that overflowed scan the list.
    if (raw_cnt > CAP) {
        const int n = min(g_ovf_cnt, OVF_CAP);
        for (int i = 0; i < n; i++) {
            const uint4 e = g_ovf[i];
            if ((int)e.x == row) {
                const float v = __uint_as_float(e.z);
                const float4 xv = __ldg(reinterpret_cast<const float4*>(
                    x + (size_t)e.y * IN_F) + lane);
                acc.x += v * xv.x; acc.y += v * xv.y;
                acc.z += v * xv.z; acc.w += v * xv.w;
            }
        }
    }

    *reinterpret_cast<float4*>(g_agg + (size_t)row * IN_F + lane * 4) = acc;
}

// ---------------------------------------------------------------------------
// K4: mma.sync bf16 split-precision GEMM + bias (proven).
// ---------------------------------------------------------------------------
#define GT 256
#define SM_BIAS 0
#define SM_AHI  1024
#define SM_ALO  (SM_AHI + 128 * PITCH * 2)
#define SM_BHI  (SM_ALO + 128 * PITCH * 2)
#define SM_BLO  (SM_BHI + OUT_F * PITCH * 2)
#define SM_TOT  (SM_BLO + OUT_F * PITCH * 2)   // 209920 B

__device__ __forceinline__ void mma16816(float c[4], uint32_t a0, uint32_t a1,
                                         uint32_t a2, uint32_t a3,
                                         uint32_t b0, uint32_t b1) {
    asm volatile(
        "mma.sync.aligned.m16n8k16.row.col.f32.bf16.bf16.f32 "
        "{%0,%1,%2,%3}, {%4,%5,%6,%7}, {%8,%9}, {%0,%1,%2,%3};"
        : "+f"(c[0]), "+f"(c[1]), "+f"(c[2]), "+f"(c[3])
        : "r"(a0), "r"(a1), "r"(a2), "r"(a3), "r"(b0), "r"(b1));
}

__global__ __launch_bounds__(GT, 1)
void gemm_mma_kernel(const float* __restrict__ bias,
                     float*       __restrict__ out) {
    extern __shared__ char smem[];
    const int t    = threadIdx.x;
    const int lane = t & 31;
    const int wid  = t >> 5;
    const int rowbase = blockIdx.x * 128;

    float* bias_s = reinterpret_cast<float*>(smem + SM_BIAS);
    __nv_bfloat16* Ahi = reinterpret_cast<__nv_bfloat16*>(smem + SM_AHI);
    __nv_bfloat16* Alo = reinterpret_cast<__nv_bfloat16*>(smem + SM_ALO);
    __nv_bfloat16* Bhi = reinterpret_cast<__nv_bfloat16*>(smem + SM_BHI);
    __nv_bfloat16* Blo = reinterpret_cast<__nv_bfloat16*>(smem + SM_BLO);

    if (t < 64)
        reinterpret_cast<float4*>(bias_s)[t] =
            reinterpret_cast<const float4*>(bias)[t];

    {
        const uint4* sh = reinterpret_cast<const uint4*>(g_Bhi);
        const uint4* sl = reinterpret_cast<const uint4*>(g_Blo);
        uint4* dh = reinterpret_cast<uint4*>(Bhi);
        uint4* dl = reinterpret_cast<uint4*>(Blo);
        #pragma unroll
        for (int i = 0; i < 17; i++) {
            dh[t + i * GT] = sh[t + i * GT];
            dl[t + i * GT] = sl[t + i * GT];
        }
    }

    #pragma unroll
    for (int i = 0; i < 8; i++) {
        const int idx = t + i * GT;
        const int kb = idx & 15;
        const int m  = idx >> 4;
        const int row = rowbase + m;

        float f[8];
        if (row < N_NODES) {
            const float4* src = reinterpret_cast<const float4*>(
                g_agg + (size_t)row * IN_F + kb * 8);
            const float4 u = src[0];
            const float4 v = src[1];
            f[0]=u.x; f[1]=u.y; f[2]=u.z; f[3]=u.w;
            f[4]=v.x; f[5]=v.y; f[6]=v.z; f[7]=v.w;
        } else {
            #pragma unroll
            for (int j = 0; j < 8; j++) f[j] = 0.f;
        }

        uint4 wh, wl;
        uint32_t* ph = reinterpret_cast<uint32_t*>(&wh);
        uint32_t* pl = reinterpret_cast<uint32_t*>(&wl);
        #pragma unroll
        for (int j = 0; j < 4; j++) {
            const __nv_bfloat16 h0 = __float2bfloat16(f[2*j]);
            const __nv_bfloat16 h1 = __float2bfloat16(f[2*j+1]);
            const __nv_bfloat16 l0 = __float2bfloat16(f[2*j]   - __bfloat162float(h0));
            const __nv_bfloat16 l1 = __float2bfloat16(f[2*j+1] - __bfloat162float(h1));
            __nv_bfloat162 hp = __halves2bfloat162(h0, h1);
            __nv_bfloat162 lp = __halves2bfloat162(l0, l1);
            ph[j] = *reinterpret_cast<uint32_t*>(&hp);
            pl[j] = *reinterpret_cast<uint32_t*>(&lp);
        }
        *reinterpret_cast<uint4*>(Ahi + m * PITCH + kb * 8) = wh;
        *reinterpret_cast<uint4*>(Alo + m * PITCH + kb * 8) = wl;
    }
    __syncthreads();

    const int wm = wid >> 2;
    const int wn = wid & 3;
    const int g  = lane >> 2;
    const int tg = lane & 3;
    const int m_base = wm * 64;
    const int n_base = wn * 64;

    float acc[4][8][4];
    #pragma unroll
    for (int mt = 0; mt < 4; mt++)
        #pragma unroll
        for (int nt = 0; nt < 8; nt++)
            #pragma unroll
            for (int j = 0; j < 4; j++)
                acc[mt][nt][j] = 0.f;

    const __nv_bfloat16* Ap[3] = {Ahi, Ahi, Alo};
    const __nv_bfloat16* Bp[3] = {Bhi, Blo, Bhi};

    #pragma unroll
    for (int pass = 0; pass < 3; pass++) {
        const __nv_bfloat16* A = Ap[pass];
        const __nv_bfloat16* B = Bp[pass];
        #pragma unroll
        for (int ks = 0; ks < IN_F; ks += 16) {
            uint32_t af[4][4];
            #pragma unroll
            for (int mt = 0; mt < 4; mt++) {
                const __nv_bfloat16* ar =
                    A + (m_base + mt * 16 + g) * PITCH + ks + tg * 2;
                af[mt][0] = *reinterpret_cast<const uint32_t*>(ar);
                af[mt][1] = *reinterpret_cast<const uint32_t*>(ar + 8 * PITCH);
                af[mt][2] = *reinterpret_cast<const uint32_t*>(ar + 8);
                af[mt][3] = *reinterpret_cast<const uint32_t*>(ar + 8 * PITCH + 8);
            }
            uint32_t bf[8][2];
            #pragma unroll
            for (int nt = 0; nt < 8; nt++) {
                const __nv_bfloat16* br =
                    B + (n_base + nt * 8 + g) * PITCH + ks + tg * 2;
                bf[nt][0] = *reinterpret_cast<const uint32_t*>(br);
                bf[nt][1] = *reinterpret_cast<const uint32_t*>(br + 8);
            }
            #pragma unroll
            for (int mt = 0; mt < 4; mt++)
                #pragma unroll
                for (int nt = 0; nt < 8; nt++)
                    mma16816(acc[mt][nt],
                             af[mt][0], af[mt][1], af[mt][2], af[mt][3],
                             bf[nt][0], bf[nt][1]);
        }
    }

    #pragma unroll
    for (int mt = 0; mt < 4; mt++) {
        const int r0 = rowbase + m_base + mt * 16 + g;
        const int r1 = r0 + 8;
        #pragma unroll
        for (int nt = 0; nt < 8; nt++) {
            const int col = n_base + nt * 8 + tg * 2;
            const float bx = bias_s[col];
            const float by = bias_s[col + 1];
            if (r0 < N_NODES) {
                float2 o = make_float2(acc[mt][nt][0] + bx, acc[mt][nt][1] + by);
                *reinterpret_cast<float2*>(out + (size_t)r0 * OUT_F + col) = o;
            }
            if (r1 < N_NODES) {
                float2 o = make_float2(acc[mt][nt][2] + bx, acc[mt][nt][3] + by);
                *reinterpret_cast<float2*>(out + (size_t)r1 * OUT_F + col) = o;
            }
        }
    }
}

// ---------------------------------------------------------------------------
// Launch
// ---------------------------------------------------------------------------
extern "C" void kernel_launch(void* const* d_in, const int* in_sizes, int n_in,
                              void* d_out, int out_size) {
    const float* x    = (const float*)d_in[0];
    const int*   erow = (const int*)  d_in[1];
    const int*   ecol = (const int*)  d_in[2];
    const float* eval = (const float*)d_in[3];
    const float* W    = (const float*)d_in[4];
    const float* bias = (const float*)d_in[5];
    float* out = (float*)d_out;

    prep_kernel<<<128, 256>>>(W);
    bin_kernel<<<(N_EDGES / 4 + 255) / 256, 256>>>(erow, ecol, eval);
    gather_kernel<<<(N_NODES + 7) / 8, 256>>>(x);

    cudaFuncSetAttribute(gemm_mma_kernel,
                         cudaFuncAttributeMaxDynamicSharedMemorySize, SM_TOT);
    const int gemm_blocks = (N_NODES + 127) / 128;   // 391
    gemm_mma_kernel<<<gemm_blocks, GT, SM_TOT>>>(bias, out);
}